// round 13
// baseline (speedup 1.0000x reference)
#include <cuda_runtime.h>
#include <cuda_fp16.h>
#include <cstdint>

// MASLoRALinear, fp16 HMMA. R11 prep/lora; k_main widened to 128x256 tiles
// (64x64 warp tiles) to cut smem traffic per output 31% -> tensor-bound.

namespace {
constexpr int Tt = 1500, Cc = 1024, Oo = 1024, Ee = 8, Rr = 16;
constexpr int Mm = 16 * Tt;          // 24000
constexpr int ER = Ee * Rr;          // 128
constexpr float SCALE = 32.0f / 16.0f;
// k_lora_h staging (128x128, BK=32)
constexpr int STAGE_L = 16384;
constexpr int NSTAGE = 3;
constexpr int DYN_SMEM_L = NSTAGE * STAGE_L;
// k_main staging (128x256, BK=32): A 8KB + B 16KB
constexpr int STAGE_M = 24576;
constexpr int DYN_SMEM_M = NSTAGE * STAGE_M;   // 72KB
}

__device__ __half g_xh[(size_t)Mm * Cc];     // 24000x1024
__device__ __half g_wbh[(size_t)Oo * Cc];    // 1024x1024
__device__ __half g_ah[(size_t)ER * Cc];     // 128x1024 (Acat)
__device__ __half g_bch[(size_t)Oo * ER];    // 1024x128 (Bcat)
__device__ __half g_Hh[(size_t)Mm * ER];     // 24000x128

// ---------------------------------------------------------------------------
__device__ __forceinline__ uint32_t smem_u32(const void* p) {
    uint32_t a;
    asm("{ .reg .u64 t; cvta.to.shared.u64 t, %1; cvt.u32.u64 %0, t; }" : "=r"(a) : "l"(p));
    return a;
}

#define CP16(s, g) \
    asm volatile("cp.async.cg.shared.global [%0], [%1], 16;" :: "r"(s), "l"(g))
#define CP_COMMIT() asm volatile("cp.async.commit_group;" ::: "memory")
#define CP_WAIT1() asm volatile("cp.async.wait_group 1;" ::: "memory")
#define CP_WAIT0() asm volatile("cp.async.wait_group 0;" ::: "memory")

#define LDSM_X4(r0, r1, r2, r3, a) \
    asm volatile("ldmatrix.sync.aligned.m8n8.x4.shared.b16 {%0,%1,%2,%3}, [%4];" \
                 : "=r"(r0), "=r"(r1), "=r"(r2), "=r"(r3) : "r"(a))

#define MMA_F16(d, a, b) \
    asm volatile("mma.sync.aligned.m16n8k16.row.col.f32.f16.f16.f32 " \
                 "{%0,%1,%2,%3},{%4,%5,%6,%7},{%8,%9},{%0,%1,%2,%3};" \
                 : "+f"((d)[0]), "+f"((d)[1]), "+f"((d)[2]), "+f"((d)[3]) \
                 : "r"((a)[0]), "r"((a)[1]), "r"((a)[2]), "r"((a)[3]), \
                   "r"((b)[0]), "r"((b)[1]))

// swizzled byte offset: 64B rows, 4x16B cols, xor swizzle
__device__ __forceinline__ uint32_t swz(int r, int c) {
    return (uint32_t)(r * 64 + ((c ^ ((r >> 1) & 3)) << 4));
}

// ---------------------------------------------------------------------------
// single prep launch: x->xh, Wb->wbh, Acat->ah, Bcat->bch  (grid-stride)
// ---------------------------------------------------------------------------
__global__ void k_prep_all(const float* __restrict__ x, const float* __restrict__ Wb,
                           const float* __restrict__ As, const float* __restrict__ Bs) {
    const int stride = gridDim.x * blockDim.x;
    const int gtid = blockIdx.x * blockDim.x + threadIdx.x;

    for (int i = gtid; i < Mm * Cc / 4; i += stride) {
        float4 v = *(const float4*)(x + (size_t)i * 4);
        __half2 h0 = __float22half2_rn(make_float2(v.x, v.y));
        __half2 h1 = __float22half2_rn(make_float2(v.z, v.w));
        *(uint2*)(g_xh + (size_t)i * 4) = make_uint2(*(uint32_t*)&h0, *(uint32_t*)&h1);
    }
    for (int i = gtid; i < Oo * Cc / 4; i += stride) {
        float4 v = *(const float4*)(Wb + (size_t)i * 4);
        __half2 h0 = __float22half2_rn(make_float2(v.x, v.y));
        __half2 h1 = __float22half2_rn(make_float2(v.z, v.w));
        *(uint2*)(g_wbh + (size_t)i * 4) = make_uint2(*(uint32_t*)&h0, *(uint32_t*)&h1);
    }
    for (int i = gtid; i < ER * Cc / 4; i += stride) {
        float4 v = *(const float4*)(As + (size_t)i * 4);
        __half2 h0 = __float22half2_rn(make_float2(v.x, v.y));
        __half2 h1 = __float22half2_rn(make_float2(v.z, v.w));
        *(uint2*)(g_ah + (size_t)i * 4) = make_uint2(*(uint32_t*)&h0, *(uint32_t*)&h1);
    }
    for (int idx = gtid; idx < Oo * ER; idx += stride) {
        int o = idx >> 7, n = idx & 127;
        g_bch[idx] = __float2half(Bs[(((size_t)(n >> 4)) * Oo + o) * Rr + (n & 15)]);
    }
}

// ---------------------------------------------------------------------------
// Kernel 1: Hh = gate-scaled (xh @ ah^T)  (R11 verbatim; 128x128, occ 2)
// ---------------------------------------------------------------------------
__global__ __launch_bounds__(256, 2)
void k_lora_h(const float* __restrict__ w) {
    extern __shared__ char dsm[];
    const uint32_t sb = smem_u32(dsm);
    const int tid = threadIdx.x;
    const int lane = tid & 31, wid = tid >> 5;
    const int wm = wid >> 2, wn = wid & 3;
    const int bm = blockIdx.x * 128;

    const int r0 = tid >> 2, cc4 = tid & 3;
    const __half* xa0 = g_xh + (size_t)min(bm + r0, Mm - 1) * Cc + cc4 * 8;
    const __half* xa1 = g_xh + (size_t)min(bm + r0 + 64, Mm - 1) * Cc + cc4 * 8;
    const __half* ab0 = g_ah + (size_t)r0 * Cc + cc4 * 8;
    const __half* ab1 = g_ah + (size_t)(r0 + 64) * Cc + cc4 * 8;
    const uint32_t o0 = swz(r0, cc4), o1 = swz(r0 + 64, cc4);

    uint32_t offA[8], offB[4];
    {
        int g = lane >> 3, wr = lane & 7;
#pragma unroll
        for (int mi = 0; mi < 4; mi++)
#pragma unroll
            for (int ks = 0; ks < 2; ks++) {
                int r = wm * 64 + mi * 16 + (g & 1) * 8 + wr;
                offA[mi * 2 + ks] = swz(r, ks * 2 + (g >> 1));
            }
#pragma unroll
        for (int j = 0; j < 2; j++)
#pragma unroll
            for (int ks = 0; ks < 2; ks++) {
                int n = wn * 32 + j * 16 + (g >> 1) * 8 + wr;
                offB[j * 2 + ks] = swz(n, ks * 2 + (g & 1));
            }
    }

    float acc[4][4][4];
#pragma unroll
    for (int a = 0; a < 4; a++)
#pragma unroll
        for (int b = 0; b < 4; b++)
#pragma unroll
            for (int c = 0; c < 4; c++) acc[a][b][c] = 0.0f;

    const int NCH = 32;
#pragma unroll
    for (int p = 0; p < 2; p++) {
        uint32_t st = sb + (uint32_t)p * STAGE_L;
        CP16(st + o0, xa0 + p * 32); CP16(st + o1, xa1 + p * 32);
        CP16(st + 8192u + o0, ab0 + p * 32); CP16(st + 8192u + o1, ab1 + p * 32);
        CP_COMMIT();
    }

#pragma unroll 1
    for (int ch = 0; ch < NCH; ch++) {
        if (ch + 1 < NCH) CP_WAIT1(); else CP_WAIT0();
        __syncthreads();
        if (ch + 2 < NCH) {
            uint32_t st = sb + (uint32_t)((ch + 2) % NSTAGE) * STAGE_L;
            CP16(st + o0, xa0 + (ch + 2) * 32); CP16(st + o1, xa1 + (ch + 2) * 32);
            CP16(st + 8192u + o0, ab0 + (ch + 2) * 32); CP16(st + 8192u + o1, ab1 + (ch + 2) * 32);
            CP_COMMIT();
        }
        const uint32_t base = sb + (uint32_t)(ch % NSTAGE) * STAGE_L;
        const uint32_t aB = base, bB = base + 8192u;
#pragma unroll
        for (int ks = 0; ks < 2; ks++) {
            uint32_t aF[4][4], bF[4][2];
#pragma unroll
            for (int mi = 0; mi < 4; mi++)
                LDSM_X4(aF[mi][0], aF[mi][1], aF[mi][2], aF[mi][3], aB + offA[mi * 2 + ks]);
#pragma unroll
            for (int j = 0; j < 2; j++) {
                uint32_t t0, t1, t2, t3;
                LDSM_X4(t0, t1, t2, t3, bB + offB[j * 2 + ks]);
                bF[2 * j][0] = t0; bF[2 * j][1] = t1;
                bF[2 * j + 1][0] = t2; bF[2 * j + 1][1] = t3;
            }
#pragma unroll
            for (int mi = 0; mi < 4; mi++)
#pragma unroll
                for (int ni = 0; ni < 4; ni++)
                    MMA_F16(acc[mi][ni], aF[mi], bF[ni]);
        }
    }

#pragma unroll
    for (int mi = 0; mi < 4; mi++) {
#pragma unroll
        for (int ni = 0; ni < 4; ni++) {
            int n = wn * 32 + ni * 8 + 2 * (lane & 3);
            int e = n >> 4;
            int m0 = bm + wm * 64 + mi * 16 + (lane >> 2);
            if (m0 < Mm) {
                float sw = SCALE * __ldg(&w[(m0 / Tt) * Ee + e]);
                __half2 h = __float22half2_rn(make_float2(acc[mi][ni][0] * sw, acc[mi][ni][1] * sw));
                *(__half2*)(&g_Hh[(size_t)m0 * ER + n]) = h;
            }
            int m1 = m0 + 8;
            if (m1 < Mm) {
                float sw = SCALE * __ldg(&w[(m1 / Tt) * Ee + e]);
                __half2 h = __float22half2_rn(make_float2(acc[mi][ni][2] * sw, acc[mi][ni][3] * sw));
                *(__half2*)(&g_Hh[(size_t)m1 * ER + n]) = h;
            }
        }
    }
}

// ---------------------------------------------------------------------------
// Kernel 2: out = xh @ wbh^T + Hh @ bch^T + bb
// 128x256 tile, 8 warps as 2(M)x4(N), warp tile 64x64. 36 chunks of BK=32.
// ---------------------------------------------------------------------------
__global__ __launch_bounds__(256, 1)
void k_main(const float* __restrict__ bb, float* __restrict__ out) {
    extern __shared__ char dsm[];
    const uint32_t sb = smem_u32(dsm);
    const int tid = threadIdx.x;
    const int lane = tid & 31, wid = tid >> 5;
    const int wm = wid >> 2, wn = wid & 3;      // wm 0..1 (64 rows), wn 0..3 (64 cols)
    const int bn = blockIdx.x * 256;
    const int bm = blockIdx.y * 128;

    // loaders: A rows r0, r0+64 (slot cc4); B rows r0+{0,64,128,192} (slot cc4)
    const int r0 = tid >> 2, cc4 = tid & 3;
    const size_t mA0 = (size_t)min(bm + r0, Mm - 1);
    const size_t mA1 = (size_t)min(bm + r0 + 64, Mm - 1);
    const __half* xa0 = g_xh + mA0 * Cc + cc4 * 8;
    const __half* xa1 = g_xh + mA1 * Cc + cc4 * 8;
    const __half* ha0 = g_Hh + mA0 * ER + cc4 * 8;
    const __half* ha1 = g_Hh + mA1 * ER + cc4 * 8;
    const __half* wbp[4];
    const __half* bcp[4];
#pragma unroll
    for (int q = 0; q < 4; q++) {
        wbp[q] = g_wbh + (size_t)(bn + r0 + q * 64) * Cc + cc4 * 8;
        bcp[q] = g_bch + (size_t)(bn + r0 + q * 64) * ER + cc4 * 8;
    }
    const uint32_t oA0 = swz(r0, cc4), oA1 = swz(r0 + 64, cc4);
    uint32_t oB[4];
#pragma unroll
    for (int q = 0; q < 4; q++) oB[q] = swz(r0 + q * 64, cc4);

    // ldmatrix offsets
    uint32_t offA[8], offB[8];
    {
        int g = lane >> 3, wr = lane & 7;
#pragma unroll
        for (int mi = 0; mi < 4; mi++)
#pragma unroll
            for (int ks = 0; ks < 2; ks++) {
                int r = wm * 64 + mi * 16 + (g & 1) * 8 + wr;
                offA[mi * 2 + ks] = swz(r, ks * 2 + (g >> 1));
            }
#pragma unroll
        for (int j = 0; j < 4; j++)
#pragma unroll
            for (int ks = 0; ks < 2; ks++) {
                int n = wn * 64 + j * 16 + (g >> 1) * 8 + wr;
                offB[j * 2 + ks] = swz(n, ks * 2 + (g & 1));
            }
    }

    float acc[4][8][4];
#pragma unroll
    for (int a = 0; a < 4; a++)
#pragma unroll
        for (int b = 0; b < 8; b++)
#pragma unroll
            for (int c = 0; c < 4; c++) acc[a][b][c] = 0.0f;

    const int NCH = 36;

    auto issue = [&](int ch) {
        uint32_t st = sb + (uint32_t)(ch % NSTAGE) * STAGE_M;
        if (ch < 32) {
            CP16(st + oA0, xa0 + ch * 32);
            CP16(st + oA1, xa1 + ch * 32);
#pragma unroll
            for (int q = 0; q < 4; q++)
                CP16(st + 8192u + oB[q], wbp[q] + ch * 32);
        } else {
            int c2 = ch - 32;
            CP16(st + oA0, ha0 + c2 * 32);
            CP16(st + oA1, ha1 + c2 * 32);
#pragma unroll
            for (int q = 0; q < 4; q++)
                CP16(st + 8192u + oB[q], bcp[q] + c2 * 32);
        }
        CP_COMMIT();
    };

    issue(0);
    issue(1);

#pragma unroll 1
    for (int ch = 0; ch < NCH; ch++) {
        if (ch + 1 < NCH) CP_WAIT1(); else CP_WAIT0();
        __syncthreads();
        if (ch + 2 < NCH) issue(ch + 2);
        const uint32_t base = sb + (uint32_t)(ch % NSTAGE) * STAGE_M;
        const uint32_t aB = base, bB = base + 8192u;
#pragma unroll
        for (int ks = 0; ks < 2; ks++) {
            uint32_t aF[4][4], bF[8][2];
#pragma unroll
            for (int mi = 0; mi < 4; mi++)
                LDSM_X4(aF[mi][0], aF[mi][1], aF[mi][2], aF[mi][3], aB + offA[mi * 2 + ks]);
#pragma unroll
            for (int j = 0; j < 4; j++) {
                uint32_t t0, t1, t2, t3;
                LDSM_X4(t0, t1, t2, t3, bB + offB[j * 2 + ks]);
                bF[2 * j][0] = t0; bF[2 * j][1] = t1;
                bF[2 * j + 1][0] = t2; bF[2 * j + 1][1] = t3;
            }
#pragma unroll
            for (int mi = 0; mi < 4; mi++)
#pragma unroll
                for (int ni = 0; ni < 8; ni++)
                    MMA_F16(acc[mi][ni], aF[mi], bF[ni]);
        }
    }

    // epilogue: add bias, store fp32
#pragma unroll
    for (int mi = 0; mi < 4; mi++) {
#pragma unroll
        for (int ni = 0; ni < 8; ni++) {
            int col = bn + wn * 64 + ni * 8 + 2 * (lane & 3);
            float2 bias = *(const float2*)(bb + col);
            int m0 = bm + wm * 64 + mi * 16 + (lane >> 2);
            if (m0 < Mm) {
                float2 o = make_float2(acc[mi][ni][0] + bias.x, acc[mi][ni][1] + bias.y);
                *(float2*)(out + (size_t)m0 * Oo + col) = o;
            }
            int m1 = m0 + 8;
            if (m1 < Mm) {
                float2 o = make_float2(acc[mi][ni][2] + bias.x, acc[mi][ni][3] + bias.y);
                *(float2*)(out + (size_t)m1 * Oo + col) = o;
            }
        }
    }
}

// ---------------------------------------------------------------------------
extern "C" void kernel_launch(void* const* d_in, const int* in_sizes, int n_in,
                              void* d_out, int out_size) {
    const float* x  = (const float*)d_in[0];   // (16,1500,1024)
    const float* w  = (const float*)d_in[1];   // (16,8)
    const float* Wb = (const float*)d_in[2];   // (1024,1024)
    const float* bb = (const float*)d_in[3];   // (1024,)
    const float* As = (const float*)d_in[4];   // (8,16,1024) = Acat (128,1024)
    const float* Bs = (const float*)d_in[5];   // (8,1024,16)
    float* out = (float*)d_out;

    cudaFuncSetAttribute(k_lora_h, cudaFuncAttributeMaxDynamicSharedMemorySize, DYN_SMEM_L);
    cudaFuncSetAttribute(k_main, cudaFuncAttributeMaxDynamicSharedMemorySize, DYN_SMEM_M);

    // ONE prep launch for all conversions (grid-stride, HBM-bound ~23us)
    k_prep_all<<<1184, 256>>>(x, Wb, As, Bs);

    const int grid_m = (Mm + 127) / 128;  // 188
    k_lora_h<<<grid_m, 256, DYN_SMEM_L>>>(w);

    dim3 g2(Oo / 256, grid_m);            // (4, 188)
    k_main<<<g2, 256, DYN_SMEM_M>>>(bb, out);
}